// round 13
// baseline (speedup 1.0000x reference)
#include <cuda_runtime.h>

#define N_B 8
#define A_N 131072
#define T_N 64
#define CAND 4096
#define NEG_TCUT 0.004f
#define APT 4
#define TPB 256
#define APB (APT * TPB)
#define C7 0.4117647058823529f   /* 0.7/1.7 */
#define C3 0.2307692307692308f   /* 0.3/1.3 */
#define TOL 1e-5f
typedef unsigned long long ull;

__device__ ull           g_gt_best[N_B * T_N];
__device__ int           g_cls   [N_B * A_N];
__device__ ull           g_thresh[N_B * 2];
__device__ int           g_tot   [N_B * 2];
__device__ int           g_ccnt  [N_B * 2];
__device__ int           g_scrub [N_B];
__device__ ull           g_cand  [N_B * 2 * CAND];

__device__ __forceinline__ void pair_iu(const float4& box, float aarea,
                                        const float4& G, float ga,
                                        float& inter, float& un) {
    float ih = fmaxf(fminf(box.z, G.z) - fmaxf(box.x, G.x), 0.f);
    float iw = fmaxf(fminf(box.w, G.w) - fmaxf(box.y, G.y), 0.f);
    inter = ih * iw;
    un = (aarea + ga) - inter;     // > 0 whenever inter > 0
}

__device__ __forceinline__ ull mk_key(float v, unsigned a) {
    return ((ull)__float_as_uint(v) << 32) | a;
}

// warp-aggregated candidate push (all lanes must call, converged)
__device__ __forceinline__ void push_cand(ull* __restrict__ buf, int* __restrict__ cnt,
                                          ull key, bool p) {
    unsigned m = __ballot_sync(0xFFFFFFFFu, p);
    if (!m) return;
    int lane = threadIdx.x & 31;
    int leader = __ffs(m) - 1;
    int base = 0;
    if (lane == leader) base = atomicAdd(cnt, __popc(m));
    base = __shfl_sync(0xFFFFFFFFu, base, leader);
    if (p) {
        int slot = base + __popc(m & ((1u << lane) - 1));
        if (slot < CAND) buf[slot] = key;
    }
}

__global__ __launch_bounds__(TPB) void k_iou(const float4* __restrict__ anchors,
                                             const float4* __restrict__ gts,
                                             const float* __restrict__ rpos,
                                             const float* __restrict__ rneg) {
    const int b   = blockIdx.y;
    const int tid = threadIdx.x;
    const int a0  = blockIdx.x * APB + tid;

    if (blockIdx.x == 0 && b == 0) {
        for (int j = tid; j < N_B * T_N; j += TPB)
            atomicMax(&g_gt_best[j], 0xFFFFFFFFull);   // (iou=0, anchor 0) floor
    }

    __shared__ float4   sgt  [T_N];
    __shared__ float    sga  [T_N];
    __shared__ unsigned sflt [T_N];   // best fl(iou) bits per gt (monotone filter)
    __shared__ unsigned sfltp[T_N];   // pre-divided filter bits: B/(1+B) * (1-1e-5)
    __shared__ ull      skey [T_N];   // packed (bits<<32 | ~anchor)
    __shared__ int      sc[2];

    if (tid < T_N) {
        float4 g = gts[b * T_N + tid];
        sgt[tid]  = g;
        sga[tid]  = (g.z - g.x) * (g.w - g.y);
        sflt[tid] = 0u;
        sfltp[tid] = 0u;
        skey[tid] = 0ull;
    }
    if (tid < 2) sc[tid] = 0;
    __syncthreads();

    float4 box[APT];
    float  aarea[APT];
    float  M7[APT], M3[APT];          // max_g (inter - c*s): sign => threshold tests
    #pragma unroll
    for (int k = 0; k < APT; ++k) {
        float4 x = anchors[b * A_N + a0 + k * TPB];
        bool inb = (x.x >= 0.f) && (x.y >= 0.f) && (x.z <= 1.f) && (x.w <= 1.f);
        if (!inb) { x.x = x.y = x.z = x.w = 0.f; }
        box[k]   = x;
        aarea[k] = (x.z - x.x) * (x.w - x.y);
        M7[k] = -4.f; M3[k] = -4.f;
    }

    // pre-warm filters with achieved IoU values (valid lower bounds)
    {
        const int g = tid & (T_N - 1);
        const float4 G = sgt[g];
        const float ga = sga[g];
        float pi = 0.f, pu = 1.f;
        #pragma unroll
        for (int k = 0; k < APT; ++k) {
            float inter, un;
            pair_iu(box[k], aarea[k], G, ga, inter, un);
            bool sw = inter * pu > pi * un;
            pi = sw ? inter : pi;
            pu = sw ? un : pu;
        }
        if (pi > 0.f) {
            float q = __fdiv_rn(pi, pu);
            atomicMax(&sflt[g], __float_as_uint(q));
            float qp = __fdiv_rn(q, 1.f + q) * (1.f - 1e-5f);
            atomicMax(&sfltp[g], __float_as_uint(qp));
        }
    }
    __syncthreads();

    #pragma unroll 1
    for (int g = 0; g < T_N; ++g) {
        const float4 G   = sgt[g];
        const float  ga  = sga[g];
        const float  cfp = __uint_as_float(sfltp[g]);
        unsigned candm = 0u;

        #pragma unroll
        for (int k = 0; k < APT; ++k) {
            float ih = fmaxf(fminf(box[k].z, G.z) - fmaxf(box[k].x, G.x), 0.f);
            float iw = fmaxf(fminf(box[k].w, G.w) - fmaxf(box[k].y, G.y), 0.f);
            float inter = ih * iw;
            float s = aarea[k] + ga;

            M7[k] = fmaxf(M7[k], fmaf(-C7, s, inter));
            M3[k] = fmaxf(M3[k], fmaf(-C3, s, inter));
            candm |= (fmaf(-cfp, s, inter) > 0.f) ? (1u << k) : 0u;
        }

        // rare resolve: one vote + branch per warp per gt
        if (__any_sync(0xFFFFFFFFu, candm)) {
            #pragma unroll
            for (int k = 0; k < APT; ++k) {
                if (candm & (1u << k)) {
                    float inter, un;
                    pair_iu(box[k], aarea[k], G, ga, inter, un);
                    if (inter > 0.f) {
                        float q = __fdiv_rn(inter, un);
                        unsigned bits = __float_as_uint(q);
                        atomicMax(&sflt[g], bits);
                        float qp = __fdiv_rn(q, 1.f + q) * (1.f - 1e-5f);
                        atomicMax(&sfltp[g], __float_as_uint(qp));
                        atomicMax(&skey[g],
                                  ((ull)bits << 32) | (0xFFFFFFFFu - (unsigned)(a0 + k * TPB)));
                    }
                }
            }
        }
    }

    // classify from signs; exact rescan only when within the tolerance band
    bool posk[APT], negk[APT];
    #pragma unroll
    for (int k = 0; k < APT; ++k) {
        float m7 = M7[k], m3 = M3[k];
        if (fabsf(m7) < TOL || fabsf(m3) < TOL) {   // rare: exact fl row max
            float q = 0.f;
            for (int g = 0; g < T_N; ++g) {
                float inter, un;
                pair_iu(box[k], aarea[k], sgt[g], sga[g], inter, un);
                float qq = (inter > 0.f) ? __fdiv_rn(inter, un) : 0.f;
                q = fmaxf(q, qq);
            }
            posk[k] = (q >= 0.7f);
            negk[k] = (q < 0.3f);
        } else {
            posk[k] = (m7 > 0.f);
            negk[k] = (m3 < 0.f);
        }
    }

    // counts + candidate pushes (converged here)
    int cpos = 0, cneg = 0;
    #pragma unroll
    for (int k = 0; k < APT; ++k) {
        const unsigned a = (unsigned)(a0 + k * TPB);
        const int i = b * A_N + a;
        const bool pos = posk[k], neg = negk[k];
        g_cls[i] = pos ? 1 : (neg ? 0 : -1);
        cpos += pos; cneg += neg;

        float rp = pos ? rpos[i] : 0.f;
        push_cand(g_cand + (b * 2 + 0) * CAND, &g_ccnt[b * 2 + 0], mk_key(rp, a), pos);
        float rn = neg ? rneg[i] : 1.f;
        push_cand(g_cand + (b * 2 + 1) * CAND, &g_ccnt[b * 2 + 1], mk_key(rn, a),
                  neg && (rn < NEG_TCUT));
    }
    #pragma unroll
    for (int s = 16; s >= 1; s >>= 1) {
        cpos += __shfl_down_sync(0xFFFFFFFFu, cpos, s);
        cneg += __shfl_down_sync(0xFFFFFFFFu, cneg, s);
    }
    if ((tid & 31) == 0) {
        if (cpos) atomicAdd(&sc[0], cpos);
        if (cneg) atomicAdd(&sc[1], cneg);
    }

    __syncthreads();
    if (tid < T_N && skey[tid] > 0xFFFFFFFFull)
        atomicMax(&g_gt_best[b * T_N + tid], skey[tid]);
    if (tid < 2 && sc[tid]) atomicAdd(&g_tot[b * 2 + tid], sc[tid]);
}

// exact radix select over the full batch (fallback; normally skipped)
__device__ ull radix_select(const float* __restrict__ r, const int* __restrict__ cls,
                            int want, int k, int* hist, int* sh) {
    ull prefix = 0;
    const int tid = threadIdx.x;
    for (int byte = 7; byte >= 0; --byte) {
        const int shift = byte * 8;
        if (tid < 256) hist[tid] = 0;
        __syncthreads();
        for (int i = tid; i < A_N; i += blockDim.x) {
            if (cls[i] == want) {
                ull key = ((ull)__float_as_uint(r[i]) << 32) | (unsigned)i;
                bool match = (byte == 7) || ((key >> (shift + 8)) == (prefix >> (shift + 8)));
                if (match) atomicAdd(&hist[(int)((key >> shift) & 0xFF)], 1);
            }
        }
        __syncthreads();
        if (tid == 0) {
            int cum = 0, d = 0;
            for (; d < 255; ++d) {
                if (cum + hist[d] >= k) break;
                cum += hist[d];
            }
            sh[0] = d;
            sh[1] = k - cum;
        }
        __syncthreads();
        prefix |= ((ull)sh[0]) << shift;
        k = sh[1];
        __syncthreads();
    }
    return prefix;
}

// fused: promote per-gt winners + rank selection + fallback
__global__ void k_pickfb(const float* __restrict__ rpos, const float* __restrict__ rneg) {
    const int b = blockIdx.x;
    const int tid = threadIdx.x;
    __shared__ ull sk[CAND];
    __shared__ int hist[256];
    __shared__ int sh[2];
    __shared__ int sfb[2];

    if (tid < T_N) {
        const unsigned a = 0xFFFFFFFFu - (unsigned)(g_gt_best[b * T_N + tid] & 0xFFFFFFFFull);
        const int i = b * A_N + a;
        const int old = atomicExch(&g_cls[i], 1);
        if (old != 1) {
            atomicAdd(&g_tot[b * 2 + 0], 1);
            int slot = atomicAdd(&g_ccnt[b * 2 + 0], 1);
            if (slot < CAND) g_cand[(b * 2 + 0) * CAND + slot] = mk_key(rpos[i], a);
            if (old == 0) {
                atomicSub(&g_tot[b * 2 + 1], 1);
                float rn = rneg[i];
                if (rn < NEG_TCUT) {
                    ull kk = mk_key(rn, a);
                    int cn = g_ccnt[b * 2 + 1];
                    if (cn > CAND) cn = CAND;
                    ull* buf = g_cand + (b * 2 + 1) * CAND;
                    for (int j = 0; j < cn; ++j)
                        if (buf[j] == kk) { buf[j] = ~0ull; atomicAdd(&g_scrub[b], 1); break; }
                }
            }
        }
    }
    if (tid == 0) { sfb[0] = 0; sfb[1] = 0; }
    __syncthreads();

    const int P  = g_tot[b * 2 + 0];
    const int cp = g_ccnt[b * 2 + 0];
    const int Nn = g_tot[b * 2 + 1];
    const int cn = g_ccnt[b * 2 + 1];
    const int scrub = g_scrub[b];
    const int npos = (P < 128) ? P : 128;
    const int Kn = 256 - npos;

    if (P <= 128) {
        if (tid == 0) g_thresh[b * 2 + 0] = ~0ull;
    } else if (cp <= CAND) {
        for (int i = tid; i < cp; i += blockDim.x) sk[i] = g_cand[(b * 2 + 0) * CAND + i];
        __syncthreads();
        for (int i = tid; i < cp; i += blockDim.x) {
            ull me = sk[i];
            int c = 0;
            for (int j = 0; j < cp; ++j) c += (sk[j] < me);
            if (c == 127) g_thresh[b * 2 + 0] = me;
        }
        __syncthreads();
    } else {
        if (tid == 0) sfb[0] = 128;
    }

    if (Nn <= Kn) {
        if (tid == 0) g_thresh[b * 2 + 1] = ~0ull;
    } else if ((cn - scrub) >= Kn && cn <= CAND) {
        __syncthreads();
        for (int i = tid; i < cn; i += blockDim.x) sk[i] = g_cand[(b * 2 + 1) * CAND + i];
        __syncthreads();
        for (int i = tid; i < cn; i += blockDim.x) {
            ull me = sk[i];
            int c = 0;
            for (int j = 0; j < cn; ++j) c += (sk[j] < me);
            if (c == Kn - 1) g_thresh[b * 2 + 1] = me;
        }
    } else {
        if (tid == 0) sfb[1] = Kn;
    }
    __syncthreads();

    const int kp = sfb[0], kn = sfb[1];
    if (kp) {
        ull t = radix_select(rpos + b * A_N, g_cls + b * A_N, 1, kp, hist, sh);
        if (tid == 0) g_thresh[b * 2 + 0] = t;
    }
    if (kn) {
        ull t = radix_select(rneg + b * A_N, g_cls + b * A_N, 0, kn, hist, sh);
        if (tid == 0) g_thresh[b * 2 + 1] = t;
    }
}

__global__ void k_out(const float4* __restrict__ anchors, const float4* __restrict__ gts,
                      const float* __restrict__ rpos, const float* __restrict__ rneg,
                      float* __restrict__ out) {
    const int b = blockIdx.y;
    const int a = blockIdx.x * blockDim.x + threadIdx.x;
    const int i = b * A_N + a;

    int cls = g_cls[i];
    if (cls == 1) {
        ull key = mk_key(rpos[i], (unsigned)a);
        if (key > g_thresh[b * 2]) cls = -1;
    } else if (cls == 0) {
        ull key = mk_key(rneg[i], (unsigned)a);
        if (key > g_thresh[b * 2 + 1]) cls = -1;
    }
    out[i] = (float)cls;

    float4 d = make_float4(0.f, 0.f, 0.f, 0.f);
    if (cls == 1) {
        float4 box = anchors[i];
        bool inb = (box.x >= 0.f) && (box.y >= 0.f) && (box.z <= 1.f) && (box.w <= 1.f);
        if (!inb) { box.x = box.y = box.z = box.w = 0.f; }
        float aarea = (box.z - box.x) * (box.w - box.y);

        // exact fl first-max argmax over gts (only ~256 anchors/batch reach here)
        float bq = 0.f; int bg = 0;
        for (int g = 0; g < T_N; ++g) {
            float4 G = gts[b * T_N + g];
            float ga = (G.z - G.x) * (G.w - G.y);
            float inter, un;
            pair_iu(box, aarea, G, ga, inter, un);
            float qq = (inter > 0.f) ? __fdiv_rn(inter, un) : 0.f;
            if (qq > bq) { bq = qq; bg = g; }
        }

        float4 gt = gts[b * T_N + bg];
        float ah = box.z - box.x, aw = box.w - box.y;
        float acy = box.x + 0.5f * ah, acx = box.y + 0.5f * aw;
        float gh = gt.z - gt.x, gw = gt.w - gt.y;
        float gcy = gt.x + 0.5f * gh, gcx = gt.y + 0.5f * gw;
        float ahs = (ah > 0.f) ? ah : 1.f;
        float aws = (aw > 0.f) ? aw : 1.f;
        float ghs = (gh > 0.f) ? gh : 1.f;
        float gws = (gw > 0.f) ? gw : 1.f;
        d.x = __fdiv_rn(gcy - acy, ahs);
        d.y = __fdiv_rn(gcx - acx, aws);
        d.z = logf(__fdiv_rn(ghs, ahs));
        d.w = logf(__fdiv_rn(gws, aws));
    }
    reinterpret_cast<float4*>(out + (size_t)N_B * A_N)[i] = d;

    // reset counters for the next graph replay
    if (blockIdx.x == 0 && b == 0) {
        const int t = threadIdx.x;
        if (t < N_B * 2) { g_tot[t] = 0; g_ccnt[t] = 0; }
        if (t >= 32 && t < 32 + N_B) g_scrub[t - 32] = 0;
    }
}

extern "C" void kernel_launch(void* const* d_in, const int* in_sizes, int n_in,
                              void* d_out, int out_size) {
    const float4* anchors = (const float4*)d_in[0];
    const float4* gts     = (const float4*)d_in[1];
    const float*  rp      = (const float*)d_in[2];
    const float*  rn      = (const float*)d_in[3];
    float* out = (float*)d_out;

    k_iou<<<dim3(A_N / APB, N_B), TPB>>>(anchors, gts, rp, rn);
    k_pickfb<<<N_B, 1024>>>(rp, rn);
    k_out<<<dim3(A_N / 256, N_B), 256>>>(anchors, gts, rp, rn, out);
}

// round 14
// speedup vs baseline: 1.0364x; 1.0364x over previous
#include <cuda_runtime.h>

#define N_B 8
#define A_N 131072
#define T_N 64
#define CAND 4096
#define NEG_TCUT 0.004f
#define APT 4
#define TPB 256
#define APB (APT * TPB)
typedef unsigned long long ull;

__device__ ull           g_gt_best[N_B * T_N];
__device__ int           g_cls   [N_B * A_N];
__device__ ull           g_thresh[N_B * 2];
__device__ int           g_tot   [N_B * 2];
__device__ int           g_ccnt  [N_B * 2];
__device__ int           g_scrub [N_B];
__device__ ull           g_cand  [N_B * 2 * CAND];

__device__ __forceinline__ void pair_iu(const float4& box, float aarea,
                                        const float4& G, float ga,
                                        float& inter, float& un) {
    float ih = fmaxf(fminf(box.z, G.z) - fmaxf(box.x, G.x), 0.f);
    float iw = fmaxf(fminf(box.w, G.w) - fmaxf(box.y, G.y), 0.f);
    inter = ih * iw;
    un = (aarea + ga) - inter;     // > 0 whenever inter > 0
}

__device__ __forceinline__ ull mk_key(float v, unsigned a) {
    return ((ull)__float_as_uint(v) << 32) | a;
}

// warp-aggregated candidate push (all lanes must call, converged)
__device__ __forceinline__ void push_cand(ull* __restrict__ buf, int* __restrict__ cnt,
                                          ull key, bool p) {
    unsigned m = __ballot_sync(0xFFFFFFFFu, p);
    if (!m) return;
    int lane = threadIdx.x & 31;
    int leader = __ffs(m) - 1;
    int base = 0;
    if (lane == leader) base = atomicAdd(cnt, __popc(m));
    base = __shfl_sync(0xFFFFFFFFu, base, leader);
    if (p) {
        int slot = base + __popc(m & ((1u << lane) - 1));
        if (slot < CAND) buf[slot] = key;
    }
}

__global__ __launch_bounds__(TPB) void k_iou(const float4* __restrict__ anchors,
                                             const float4* __restrict__ gts,
                                             const float* __restrict__ rpos,
                                             const float* __restrict__ rneg) {
    const int b   = blockIdx.y;
    const int tid = threadIdx.x;
    const int a0  = blockIdx.x * APB + tid;

    if (blockIdx.x == 0 && b == 0) {
        for (int j = tid; j < N_B * T_N; j += TPB)
            atomicMax(&g_gt_best[j], 0xFFFFFFFFull);   // (iou=0, anchor 0) floor
    }

    __shared__ float4   sgt [T_N];
    __shared__ float    sga [T_N];
    __shared__ unsigned sflt[T_N];   // running best fl(iou) bits per gt (monotone filter)
    __shared__ ull      skey[T_N];   // packed (bits<<32 | ~anchor)
    __shared__ int      sc[2];

    if (tid < T_N) {
        float4 g = gts[b * T_N + tid];
        sgt[tid] = g;
        sga[tid] = (g.z - g.x) * (g.w - g.y);
        sflt[tid] = 0u;
        skey[tid] = 0ull;
    }
    if (tid < 2) sc[tid] = 0;
    __syncthreads();

    float4 box[APT];
    float  aarea[APT];
    float  bi[APT], bu[APT];          // approx running row max as (inter, union) pair
    #pragma unroll
    for (int k = 0; k < APT; ++k) {
        float4 x = anchors[b * A_N + a0 + k * TPB];
        bool inb = (x.x >= 0.f) && (x.y >= 0.f) && (x.z <= 1.f) && (x.w <= 1.f);
        if (!inb) { x.x = x.y = x.z = x.w = 0.f; }
        box[k]   = x;
        aarea[k] = (x.z - x.x) * (x.w - x.y);
        bi[k] = 0.f; bu[k] = 1.f;
    }

    // pre-warm column filter with achieved IoU values (valid lower bounds)
    {
        const int g = tid & (T_N - 1);
        const float4 G = sgt[g];
        const float ga = sga[g];
        float pi = 0.f, pu = 1.f;
        #pragma unroll
        for (int k = 0; k < APT; ++k) {
            float inter, un;
            pair_iu(box[k], aarea[k], G, ga, inter, un);
            bool sw = inter * pu > pi * un;
            pi = sw ? inter : pi;
            pu = sw ? un : pu;
        }
        if (pi > 0.f)
            atomicMax(&sflt[g], __float_as_uint(__fdiv_rn(pi, pu)));
    }
    __syncthreads();

    #pragma unroll 2
    for (int g = 0; g < T_N; ++g) {
        const float4 G  = sgt[g];
        const float  ga = sga[g];
        const float  cf = __uint_as_float(sflt[g]) * 0.9999995f;  // margin keeps fl-ties
        unsigned candm = 0u;

        #pragma unroll
        for (int k = 0; k < APT; ++k) {
            float ih = fmaxf(fminf(box[k].z, G.z) - fmaxf(box[k].x, G.x), 0.f);
            float iw = fmaxf(fminf(box[k].w, G.w) - fmaxf(box[k].y, G.y), 0.f);
            float inter = ih * iw;
            float un = (aarea[k] + ga) - inter;

            // approx row max (no argmax, no band): within ~1.5e-5 rel of true max
            bool sw = inter * bu[k] > bi[k] * un;
            bi[k] = sw ? inter : bi[k];
            bu[k] = sw ? un    : bu[k];

            // column (per-gt) candidate bit
            candm |= (inter > cf * un) ? (1u << k) : 0u;
        }

        // rare resolve: one vote + branch per warp per gt
        if (__any_sync(0xFFFFFFFFu, candm)) {
            #pragma unroll
            for (int k = 0; k < APT; ++k) {
                if (candm & (1u << k)) {
                    float inter, un;
                    pair_iu(box[k], aarea[k], G, ga, inter, un);
                    if (inter > 0.f) {
                        unsigned bits = __float_as_uint(__fdiv_rn(inter, un));
                        atomicMax(&sflt[g], bits);
                        atomicMax(&skey[g],
                                  ((ull)bits << 32) | (0xFFFFFFFFu - (unsigned)(a0 + k * TPB)));
                    }
                }
            }
        }
    }

    // classify: one divide per anchor; exact rescan only near thresholds (~1e-4)
    int cpos = 0, cneg = 0;
    #pragma unroll
    for (int k = 0; k < APT; ++k) {
        float qb = (bi[k] > 0.f) ? __fdiv_rn(bi[k], bu[k]) : 0.f;
        if (fabsf(qb - 0.3f) < 3e-5f || fabsf(qb - 0.7f) < 3e-5f) {
            float q = 0.f;                      // exact fl max of the row
            for (int g = 0; g < T_N; ++g) {
                float inter, un;
                pair_iu(box[k], aarea[k], sgt[g], sga[g], inter, un);
                float qq = (inter > 0.f) ? __fdiv_rn(inter, un) : 0.f;
                q = fmaxf(q, qq);
            }
            qb = q;
        }
        const unsigned a = (unsigned)(a0 + k * TPB);
        const int i = b * A_N + a;
        const bool pos = (qb >= 0.7f);
        const bool neg = (qb < 0.3f);
        g_cls[i] = pos ? 1 : (neg ? 0 : -1);
        cpos += pos; cneg += neg;

        float rp = pos ? rpos[i] : 0.f;
        push_cand(g_cand + (b * 2 + 0) * CAND, &g_ccnt[b * 2 + 0], mk_key(rp, a), pos);
        float rn = neg ? rneg[i] : 1.f;
        push_cand(g_cand + (b * 2 + 1) * CAND, &g_ccnt[b * 2 + 1], mk_key(rn, a),
                  neg && (rn < NEG_TCUT));
    }
    #pragma unroll
    for (int s = 16; s >= 1; s >>= 1) {
        cpos += __shfl_down_sync(0xFFFFFFFFu, cpos, s);
        cneg += __shfl_down_sync(0xFFFFFFFFu, cneg, s);
    }
    if ((tid & 31) == 0) {
        if (cpos) atomicAdd(&sc[0], cpos);
        if (cneg) atomicAdd(&sc[1], cneg);
    }

    __syncthreads();
    if (tid < T_N && skey[tid] > 0xFFFFFFFFull)
        atomicMax(&g_gt_best[b * T_N + tid], skey[tid]);
    if (tid < 2 && sc[tid]) atomicAdd(&g_tot[b * 2 + tid], sc[tid]);
}

// exact radix select over the full batch (fallback; normally skipped)
__device__ ull radix_select(const float* __restrict__ r, const int* __restrict__ cls,
                            int want, int k, int* hist, int* sh) {
    ull prefix = 0;
    const int tid = threadIdx.x;
    for (int byte = 7; byte >= 0; --byte) {
        const int shift = byte * 8;
        if (tid < 256) hist[tid] = 0;
        __syncthreads();
        for (int i = tid; i < A_N; i += blockDim.x) {
            if (cls[i] == want) {
                ull key = ((ull)__float_as_uint(r[i]) << 32) | (unsigned)i;
                bool match = (byte == 7) || ((key >> (shift + 8)) == (prefix >> (shift + 8)));
                if (match) atomicAdd(&hist[(int)((key >> shift) & 0xFF)], 1);
            }
        }
        __syncthreads();
        if (tid == 0) {
            int cum = 0, d = 0;
            for (; d < 255; ++d) {
                if (cum + hist[d] >= k) break;
                cum += hist[d];
            }
            sh[0] = d;
            sh[1] = k - cum;
        }
        __syncthreads();
        prefix |= ((ull)sh[0]) << shift;
        k = sh[1];
        __syncthreads();
    }
    return prefix;
}

// fused: promote per-gt winners + rank selection + fallback
__global__ void k_pickfb(const float* __restrict__ rpos, const float* __restrict__ rneg) {
    const int b = blockIdx.x;
    const int tid = threadIdx.x;
    __shared__ ull sk[CAND];
    __shared__ int hist[256];
    __shared__ int sh[2];
    __shared__ int sfb[2];

    if (tid < T_N) {
        const unsigned a = 0xFFFFFFFFu - (unsigned)(g_gt_best[b * T_N + tid] & 0xFFFFFFFFull);
        const int i = b * A_N + a;
        const int old = atomicExch(&g_cls[i], 1);
        if (old != 1) {
            atomicAdd(&g_tot[b * 2 + 0], 1);
            int slot = atomicAdd(&g_ccnt[b * 2 + 0], 1);
            if (slot < CAND) g_cand[(b * 2 + 0) * CAND + slot] = mk_key(rpos[i], a);
            if (old == 0) {
                atomicSub(&g_tot[b * 2 + 1], 1);
                float rn = rneg[i];
                if (rn < NEG_TCUT) {
                    ull kk = mk_key(rn, a);
                    int cn = g_ccnt[b * 2 + 1];
                    if (cn > CAND) cn = CAND;
                    ull* buf = g_cand + (b * 2 + 1) * CAND;
                    for (int j = 0; j < cn; ++j)
                        if (buf[j] == kk) { buf[j] = ~0ull; atomicAdd(&g_scrub[b], 1); break; }
                }
            }
        }
    }
    if (tid == 0) { sfb[0] = 0; sfb[1] = 0; }
    __syncthreads();

    const int P  = g_tot[b * 2 + 0];
    const int cp = g_ccnt[b * 2 + 0];
    const int Nn = g_tot[b * 2 + 1];
    const int cn = g_ccnt[b * 2 + 1];
    const int scrub = g_scrub[b];
    const int npos = (P < 128) ? P : 128;
    const int Kn = 256 - npos;

    if (P <= 128) {
        if (tid == 0) g_thresh[b * 2 + 0] = ~0ull;
    } else if (cp <= CAND) {
        for (int i = tid; i < cp; i += blockDim.x) sk[i] = g_cand[(b * 2 + 0) * CAND + i];
        __syncthreads();
        for (int i = tid; i < cp; i += blockDim.x) {
            ull me = sk[i];
            int c = 0;
            for (int j = 0; j < cp; ++j) c += (sk[j] < me);
            if (c == 127) g_thresh[b * 2 + 0] = me;
        }
        __syncthreads();
    } else {
        if (tid == 0) sfb[0] = 128;
    }

    if (Nn <= Kn) {
        if (tid == 0) g_thresh[b * 2 + 1] = ~0ull;
    } else if ((cn - scrub) >= Kn && cn <= CAND) {
        __syncthreads();
        for (int i = tid; i < cn; i += blockDim.x) sk[i] = g_cand[(b * 2 + 1) * CAND + i];
        __syncthreads();
        for (int i = tid; i < cn; i += blockDim.x) {
            ull me = sk[i];
            int c = 0;
            for (int j = 0; j < cn; ++j) c += (sk[j] < me);
            if (c == Kn - 1) g_thresh[b * 2 + 1] = me;
        }
    } else {
        if (tid == 0) sfb[1] = Kn;
    }
    __syncthreads();

    const int kp = sfb[0], kn = sfb[1];
    if (kp) {
        ull t = radix_select(rpos + b * A_N, g_cls + b * A_N, 1, kp, hist, sh);
        if (tid == 0) g_thresh[b * 2 + 0] = t;
    }
    if (kn) {
        ull t = radix_select(rneg + b * A_N, g_cls + b * A_N, 0, kn, hist, sh);
        if (tid == 0) g_thresh[b * 2 + 1] = t;
    }
}

__global__ void k_out(const float4* __restrict__ anchors, const float4* __restrict__ gts,
                      const float* __restrict__ rpos, const float* __restrict__ rneg,
                      float* __restrict__ out) {
    const int b = blockIdx.y;
    const int a = blockIdx.x * blockDim.x + threadIdx.x;
    const int i = b * A_N + a;

    int cls = g_cls[i];
    if (cls == 1) {
        ull key = mk_key(rpos[i], (unsigned)a);
        if (key > g_thresh[b * 2]) cls = -1;
    } else if (cls == 0) {
        ull key = mk_key(rneg[i], (unsigned)a);
        if (key > g_thresh[b * 2 + 1]) cls = -1;
    }
    out[i] = (float)cls;

    float4 d = make_float4(0.f, 0.f, 0.f, 0.f);
    if (cls == 1) {
        float4 box = anchors[i];
        bool inb = (box.x >= 0.f) && (box.y >= 0.f) && (box.z <= 1.f) && (box.w <= 1.f);
        if (!inb) { box.x = box.y = box.z = box.w = 0.f; }
        float aarea = (box.z - box.x) * (box.w - box.y);

        // exact fl first-max argmax over gts (only ~256 anchors/batch reach here)
        float bq = 0.f; int bg = 0;
        for (int g = 0; g < T_N; ++g) {
            float4 G = gts[b * T_N + g];
            float ga = (G.z - G.x) * (G.w - G.y);
            float inter, un;
            pair_iu(box, aarea, G, ga, inter, un);
            float qq = (inter > 0.f) ? __fdiv_rn(inter, un) : 0.f;
            if (qq > bq) { bq = qq; bg = g; }
        }

        float4 gt = gts[b * T_N + bg];
        float ah = box.z - box.x, aw = box.w - box.y;
        float acy = box.x + 0.5f * ah, acx = box.y + 0.5f * aw;
        float gh = gt.z - gt.x, gw = gt.w - gt.y;
        float gcy = gt.x + 0.5f * gh, gcx = gt.y + 0.5f * gw;
        float ahs = (ah > 0.f) ? ah : 1.f;
        float aws = (aw > 0.f) ? aw : 1.f;
        float ghs = (gh > 0.f) ? gh : 1.f;
        float gws = (gw > 0.f) ? gw : 1.f;
        d.x = __fdiv_rn(gcy - acy, ahs);
        d.y = __fdiv_rn(gcx - acx, aws);
        d.z = logf(__fdiv_rn(ghs, ahs));
        d.w = logf(__fdiv_rn(gws, aws));
    }
    reinterpret_cast<float4*>(out + (size_t)N_B * A_N)[i] = d;

    // reset counters for the next graph replay
    if (blockIdx.x == 0 && b == 0) {
        const int t = threadIdx.x;
        if (t < N_B * 2) { g_tot[t] = 0; g_ccnt[t] = 0; }
        if (t >= 32 && t < 32 + N_B) g_scrub[t - 32] = 0;
    }
}

extern "C" void kernel_launch(void* const* d_in, const int* in_sizes, int n_in,
                              void* d_out, int out_size) {
    const float4* anchors = (const float4*)d_in[0];
    const float4* gts     = (const float4*)d_in[1];
    const float*  rp      = (const float*)d_in[2];
    const float*  rn      = (const float*)d_in[3];
    float* out = (float*)d_out;

    k_iou<<<dim3(A_N / APB, N_B), TPB>>>(anchors, gts, rp, rn);
    k_pickfb<<<N_B, 1024>>>(rp, rn);
    k_out<<<dim3(A_N / 256, N_B), 256>>>(anchors, gts, rp, rn, out);
}

// round 16
// speedup vs baseline: 1.0588x; 1.0216x over previous
#include <cuda_runtime.h>

#define N_B 8
#define A_N 131072
#define T_N 64
#define CAND 4096
#define NEG_TCUT 0.004f
#define APT 4
#define TPB 256
#define APB (APT * TPB)
typedef unsigned long long ull;

__device__ ull           g_gt_best[N_B * T_N];
__device__ int           g_cls   [N_B * A_N];
__device__ ull           g_thresh[N_B * 2];
__device__ int           g_tot   [N_B * 2];
__device__ int           g_ccnt  [N_B * 2];
__device__ int           g_scrub [N_B];
__device__ ull           g_cand  [N_B * 2 * CAND];

__device__ __forceinline__ void pair_iu(const float4& box, float aarea,
                                        const float4& G, float ga,
                                        float& inter, float& un) {
    float ih = fmaxf(fminf(box.z, G.z) - fmaxf(box.x, G.x), 0.f);
    float iw = fmaxf(fminf(box.w, G.w) - fmaxf(box.y, G.y), 0.f);
    inter = ih * iw;
    un = (aarea + ga) - inter;     // > 0 whenever inter > 0
}

__device__ __forceinline__ ull mk_key(float v, unsigned a) {
    return ((ull)__float_as_uint(v) << 32) | a;
}

// warp-aggregated candidate push (all lanes must call, converged)
__device__ __forceinline__ void push_cand(ull* __restrict__ buf, int* __restrict__ cnt,
                                          ull key, bool p) {
    unsigned m = __ballot_sync(0xFFFFFFFFu, p);
    if (!m) return;
    int lane = threadIdx.x & 31;
    int leader = __ffs(m) - 1;
    int base = 0;
    if (lane == leader) base = atomicAdd(cnt, __popc(m));
    base = __shfl_sync(0xFFFFFFFFu, base, leader);
    if (p) {
        int slot = base + __popc(m & ((1u << lane) - 1));
        if (slot < CAND) buf[slot] = key;
    }
}

__global__ __launch_bounds__(TPB) void k_iou(const float4* __restrict__ anchors,
                                             const float4* __restrict__ gts,
                                             const float* __restrict__ rpos,
                                             const float* __restrict__ rneg) {
    const int b   = blockIdx.y;
    const int tid = threadIdx.x;
    const int a0  = blockIdx.x * APB + tid;

    if (blockIdx.x == 0 && b == 0) {
        for (int j = tid; j < N_B * T_N; j += TPB)
            atomicMax(&g_gt_best[j], 0xFFFFFFFFull);   // (iou=0, anchor 0) floor
    }

    __shared__ float4   sgt [T_N];
    __shared__ float    sga [T_N];
    __shared__ unsigned sflt[T_N];   // running best r = inter/s bits per gt (monotone)
    __shared__ ull      skey[T_N];   // packed (fl(iou) bits<<32 | ~anchor)
    __shared__ int      sc[2];

    if (tid < T_N) {
        float4 g = gts[b * T_N + tid];
        sgt[tid] = g;
        sga[tid] = (g.z - g.x) * (g.w - g.y);
        sflt[tid] = 0u;
        skey[tid] = 0ull;
    }
    if (tid < 2) sc[tid] = 0;
    __syncthreads();

    float4 box[APT];
    float  aarea[APT];
    float  bi[APT], bs[APT];          // approx running row max as (inter, s) pair
    #pragma unroll
    for (int k = 0; k < APT; ++k) {
        float4 x = anchors[b * A_N + a0 + k * TPB];
        bool inb = (x.x >= 0.f) && (x.y >= 0.f) && (x.z <= 1.f) && (x.w <= 1.f);
        if (!inb) { x.x = x.y = x.z = x.w = 0.f; }
        box[k]   = x;
        aarea[k] = (x.z - x.x) * (x.w - x.y);
        bi[k] = 0.f; bs[k] = 1.f;
    }

    // pre-warm column filter with achieved r values (valid lower bounds)
    {
        const int g = tid & (T_N - 1);
        const float4 G = sgt[g];
        const float ga = sga[g];
        float pi = 0.f, ps = 1.f;
        #pragma unroll
        for (int k = 0; k < APT; ++k) {
            float ih = fmaxf(fminf(box[k].z, G.z) - fmaxf(box[k].x, G.x), 0.f);
            float iw = fmaxf(fminf(box[k].w, G.w) - fmaxf(box[k].y, G.y), 0.f);
            float inter = ih * iw;
            float s = aarea[k] + ga;
            bool sw = inter * ps > pi * s;
            pi = sw ? inter : pi;
            ps = sw ? s : ps;
        }
        if (pi > 0.f)
            atomicMax(&sflt[g], __float_as_uint(__fdiv_rn(pi, ps)));
    }
    __syncthreads();

    #pragma unroll 1
    for (int g = 0; g < T_N; ++g) {
        const float4 G   = sgt[g];
        const float  ga  = sga[g];
        const float  cfr = __uint_as_float(sflt[g]) * 0.9999995f;  // r-space, keeps fl-ties
        unsigned candm = 0u;

        #pragma unroll
        for (int k = 0; k < APT; ++k) {
            float ih = fmaxf(fminf(box[k].z, G.z) - fmaxf(box[k].x, G.x), 0.f);
            float iw = fminf(box[k].w, G.w) - fmaxf(box[k].y, G.y);   // unclamped: inter<0 fails all tests
            float inter = ih * iw;
            float s = aarea[k] + ga;

            // approx row max: q-order == r-order; inter·inter terms cancel
            bool sw = inter * bs[k] > bi[k] * s;
            bi[k] = sw ? inter : bi[k];
            bs[k] = sw ? s     : bs[k];

            // column candidate bit (r-space filter)
            candm |= (inter > cfr * s) ? (1u << k) : 0u;
        }

        // rare resolve: one vote + branch per warp per gt
        if (__any_sync(0xFFFFFFFFu, candm)) {
            #pragma unroll
            for (int k = 0; k < APT; ++k) {
                if (candm & (1u << k)) {
                    float inter, un;
                    pair_iu(box[k], aarea[k], G, ga, inter, un);
                    if (inter > 0.f) {
                        float s = aarea[k] + ga;
                        atomicMax(&sflt[g], __float_as_uint(__fdiv_rn(inter, s)));
                        unsigned bits = __float_as_uint(__fdiv_rn(inter, un));
                        atomicMax(&skey[g],
                                  ((ull)bits << 32) | (0xFFFFFFFFu - (unsigned)(a0 + k * TPB)));
                    }
                }
            }
        }
    }

    // classify: one divide per anchor; exact rescan only near thresholds (~1e-4)
    int cpos = 0, cneg = 0;
    #pragma unroll
    for (int k = 0; k < APT; ++k) {
        float qb = (bi[k] > 0.f) ? __fdiv_rn(bi[k], bs[k] - bi[k]) : 0.f;  // == bi/bu of winner
        if (fabsf(qb - 0.3f) < 3e-5f || fabsf(qb - 0.7f) < 3e-5f) {
            float q = 0.f;                      // exact fl max of the row
            for (int g = 0; g < T_N; ++g) {
                float inter, un;
                pair_iu(box[k], aarea[k], sgt[g], sga[g], inter, un);
                float qq = (inter > 0.f) ? __fdiv_rn(inter, un) : 0.f;
                q = fmaxf(q, qq);
            }
            qb = q;
        }
        const unsigned a = (unsigned)(a0 + k * TPB);
        const int i = b * A_N + a;
        const bool pos = (qb >= 0.7f);
        const bool neg = (qb < 0.3f);
        g_cls[i] = pos ? 1 : (neg ? 0 : -1);
        cpos += pos; cneg += neg;

        float rp = pos ? rpos[i] : 0.f;
        push_cand(g_cand + (b * 2 + 0) * CAND, &g_ccnt[b * 2 + 0], mk_key(rp, a), pos);
        float rn = neg ? rneg[i] : 1.f;
        push_cand(g_cand + (b * 2 + 1) * CAND, &g_ccnt[b * 2 + 1], mk_key(rn, a),
                  neg && (rn < NEG_TCUT));
    }
    #pragma unroll
    for (int s = 16; s >= 1; s >>= 1) {
        cpos += __shfl_down_sync(0xFFFFFFFFu, cpos, s);
        cneg += __shfl_down_sync(0xFFFFFFFFu, cneg, s);
    }
    if ((tid & 31) == 0) {
        if (cpos) atomicAdd(&sc[0], cpos);
        if (cneg) atomicAdd(&sc[1], cneg);
    }

    __syncthreads();
    if (tid < T_N && skey[tid] > 0xFFFFFFFFull)
        atomicMax(&g_gt_best[b * T_N + tid], skey[tid]);
    if (tid < 2 && sc[tid]) atomicAdd(&g_tot[b * 2 + tid], sc[tid]);
}

// exact radix select over the full batch (fallback; normally skipped)
__device__ ull radix_select(const float* __restrict__ r, const int* __restrict__ cls,
                            int want, int k, int* hist, int* sh) {
    ull prefix = 0;
    const int tid = threadIdx.x;
    for (int byte = 7; byte >= 0; --byte) {
        const int shift = byte * 8;
        if (tid < 256) hist[tid] = 0;
        __syncthreads();
        for (int i = tid; i < A_N; i += blockDim.x) {
            if (cls[i] == want) {
                ull key = ((ull)__float_as_uint(r[i]) << 32) | (unsigned)i;
                bool match = (byte == 7) || ((key >> (shift + 8)) == (prefix >> (shift + 8)));
                if (match) atomicAdd(&hist[(int)((key >> shift) & 0xFF)], 1);
            }
        }
        __syncthreads();
        if (tid == 0) {
            int cum = 0, d = 0;
            for (; d < 255; ++d) {
                if (cum + hist[d] >= k) break;
                cum += hist[d];
            }
            sh[0] = d;
            sh[1] = k - cum;
        }
        __syncthreads();
        prefix |= ((ull)sh[0]) << shift;
        k = sh[1];
        __syncthreads();
    }
    return prefix;
}

// fused: promote per-gt winners + rank selection + fallback
__global__ void k_pickfb(const float* __restrict__ rpos, const float* __restrict__ rneg) {
    const int b = blockIdx.x;
    const int tid = threadIdx.x;
    __shared__ ull sk[CAND];
    __shared__ int hist[256];
    __shared__ int sh[2];
    __shared__ int sfb[2];

    if (tid < T_N) {
        const unsigned a = 0xFFFFFFFFu - (unsigned)(g_gt_best[b * T_N + tid] & 0xFFFFFFFFull);
        const int i = b * A_N + a;
        const int old = atomicExch(&g_cls[i], 1);
        if (old != 1) {
            atomicAdd(&g_tot[b * 2 + 0], 1);
            int slot = atomicAdd(&g_ccnt[b * 2 + 0], 1);
            if (slot < CAND) g_cand[(b * 2 + 0) * CAND + slot] = mk_key(rpos[i], a);
            if (old == 0) {
                atomicSub(&g_tot[b * 2 + 1], 1);
                float rn = rneg[i];
                if (rn < NEG_TCUT) {
                    ull kk = mk_key(rn, a);
                    int cn = g_ccnt[b * 2 + 1];
                    if (cn > CAND) cn = CAND;
                    ull* buf = g_cand + (b * 2 + 1) * CAND;
                    for (int j = 0; j < cn; ++j)
                        if (buf[j] == kk) { buf[j] = ~0ull; atomicAdd(&g_scrub[b], 1); break; }
                }
            }
        }
    }
    if (tid == 0) { sfb[0] = 0; sfb[1] = 0; }
    __syncthreads();

    const int P  = g_tot[b * 2 + 0];
    const int cp = g_ccnt[b * 2 + 0];
    const int Nn = g_tot[b * 2 + 1];
    const int cn = g_ccnt[b * 2 + 1];
    const int scrub = g_scrub[b];
    const int npos = (P < 128) ? P : 128;
    const int Kn = 256 - npos;

    if (P <= 128) {
        if (tid == 0) g_thresh[b * 2 + 0] = ~0ull;
    } else if (cp <= CAND) {
        for (int i = tid; i < cp; i += blockDim.x) sk[i] = g_cand[(b * 2 + 0) * CAND + i];
        __syncthreads();
        for (int i = tid; i < cp; i += blockDim.x) {
            ull me = sk[i];
            int c = 0;
            for (int j = 0; j < cp; ++j) c += (sk[j] < me);
            if (c == 127) g_thresh[b * 2 + 0] = me;
        }
        __syncthreads();
    } else {
        if (tid == 0) sfb[0] = 128;
    }

    if (Nn <= Kn) {
        if (tid == 0) g_thresh[b * 2 + 1] = ~0ull;
    } else if ((cn - scrub) >= Kn && cn <= CAND) {
        __syncthreads();
        for (int i = tid; i < cn; i += blockDim.x) sk[i] = g_cand[(b * 2 + 1) * CAND + i];
        __syncthreads();
        for (int i = tid; i < cn; i += blockDim.x) {
            ull me = sk[i];
            int c = 0;
            for (int j = 0; j < cn; ++j) c += (sk[j] < me);
            if (c == Kn - 1) g_thresh[b * 2 + 1] = me;
        }
    } else {
        if (tid == 0) sfb[1] = Kn;
    }
    __syncthreads();

    const int kp = sfb[0], kn = sfb[1];
    if (kp) {
        ull t = radix_select(rpos + b * A_N, g_cls + b * A_N, 1, kp, hist, sh);
        if (tid == 0) g_thresh[b * 2 + 0] = t;
    }
    if (kn) {
        ull t = radix_select(rneg + b * A_N, g_cls + b * A_N, 0, kn, hist, sh);
        if (tid == 0) g_thresh[b * 2 + 1] = t;
    }
}

__global__ void k_out(const float4* __restrict__ anchors, const float4* __restrict__ gts,
                      const float* __restrict__ rpos, const float* __restrict__ rneg,
                      float* __restrict__ out) {
    const int b = blockIdx.y;
    const int a = blockIdx.x * blockDim.x + threadIdx.x;
    const int i = b * A_N + a;

    int cls = g_cls[i];
    if (cls == 1) {
        ull key = mk_key(rpos[i], (unsigned)a);
        if (key > g_thresh[b * 2]) cls = -1;
    } else if (cls == 0) {
        ull key = mk_key(rneg[i], (unsigned)a);
        if (key > g_thresh[b * 2 + 1]) cls = -1;
    }
    out[i] = (float)cls;

    float4 d = make_float4(0.f, 0.f, 0.f, 0.f);
    if (cls == 1) {
        float4 box = anchors[i];
        bool inb = (box.x >= 0.f) && (box.y >= 0.f) && (box.z <= 1.f) && (box.w <= 1.f);
        if (!inb) { box.x = box.y = box.z = box.w = 0.f; }
        float aarea = (box.z - box.x) * (box.w - box.y);

        // exact fl first-max argmax over gts (only ~256 anchors/batch reach here)
        float bq = 0.f; int bg = 0;
        for (int g = 0; g < T_N; ++g) {
            float4 G = gts[b * T_N + g];
            float ga = (G.z - G.x) * (G.w - G.y);
            float inter, un;
            pair_iu(box, aarea, G, ga, inter, un);
            float qq = (inter > 0.f) ? __fdiv_rn(inter, un) : 0.f;
            if (qq > bq) { bq = qq; bg = g; }
        }

        float4 gt = gts[b * T_N + bg];
        float ah = box.z - box.x, aw = box.w - box.y;
        float acy = box.x + 0.5f * ah, acx = box.y + 0.5f * aw;
        float gh = gt.z - gt.x, gw = gt.w - gt.y;
        float gcy = gt.x + 0.5f * gh, gcx = gt.y + 0.5f * gw;
        float ahs = (ah > 0.f) ? ah : 1.f;
        float aws = (aw > 0.f) ? aw : 1.f;
        float ghs = (gh > 0.f) ? gh : 1.f;
        float gws = (gw > 0.f) ? gw : 1.f;
        d.x = __fdiv_rn(gcy - acy, ahs);
        d.y = __fdiv_rn(gcx - acx, aws);
        d.z = logf(__fdiv_rn(ghs, ahs));
        d.w = logf(__fdiv_rn(gws, aws));
    }
    reinterpret_cast<float4*>(out + (size_t)N_B * A_N)[i] = d;

    // reset counters for the next graph replay
    if (blockIdx.x == 0 && b == 0) {
        const int t = threadIdx.x;
        if (t < N_B * 2) { g_tot[t] = 0; g_ccnt[t] = 0; }
        if (t >= 32 && t < 32 + N_B) g_scrub[t - 32] = 0;
    }
}

extern "C" void kernel_launch(void* const* d_in, const int* in_sizes, int n_in,
                              void* d_out, int out_size) {
    const float4* anchors = (const float4*)d_in[0];
    const float4* gts     = (const float4*)d_in[1];
    const float*  rp      = (const float*)d_in[2];
    const float*  rn      = (const float*)d_in[3];
    float* out = (float*)d_out;

    k_iou<<<dim3(A_N / APB, N_B), TPB>>>(anchors, gts, rp, rn);
    k_pickfb<<<N_B, 1024>>>(rp, rn);
    k_out<<<dim3(A_N / 256, N_B), 256>>>(anchors, gts, rp, rn, out);
}